// round 1
// baseline (speedup 1.0000x reference)
#include <cuda_runtime.h>

#define FEAT 8

template<int RES>
__device__ __forceinline__ void lerp_add(const float* __restrict__ cb,
                                         float px, float py, float pz,
                                         float4& a0, float4& a1)
{
    const float s = (float)(RES - 1);
    float x = px * s, y = py * s, z = pz * s;

    float fx0 = floorf(x), fy0 = floorf(y), fz0 = floorf(z);
    fx0 = fminf(fmaxf(fx0, 0.0f), (float)(RES - 2));
    fy0 = fminf(fmaxf(fy0, 0.0f), (float)(RES - 2));
    fz0 = fminf(fmaxf(fz0, 0.0f), (float)(RES - 2));

    int x0 = (int)fx0, y0 = (int)fy0, z0 = (int)fz0;
    float fx = x - fx0, fy = y - fy0, fz = z - fz0;

    float wx[2] = {1.0f - fx, fx};
    float wy[2] = {1.0f - fy, fy};
    float wz[2] = {1.0f - fz, fz};

    int base = x0 + y0 * RES + z0 * (RES * RES);

    #pragma unroll
    for (int dz = 0; dz < 2; ++dz) {
        #pragma unroll
        for (int dy = 0; dy < 2; ++dy) {
            #pragma unroll
            for (int dx = 0; dx < 2; ++dx) {
                int idx = base + dx + dy * RES + dz * (RES * RES);
                float w = wx[dx] * wy[dy] * wz[dz];
                const float4* p = reinterpret_cast<const float4*>(cb + (size_t)idx * FEAT);
                float4 v0 = __ldg(p);
                float4 v1 = __ldg(p + 1);
                a0.x = fmaf(w, v0.x, a0.x);
                a0.y = fmaf(w, v0.y, a0.y);
                a0.z = fmaf(w, v0.z, a0.z);
                a0.w = fmaf(w, v0.w, a0.w);
                a1.x = fmaf(w, v1.x, a1.x);
                a1.y = fmaf(w, v1.y, a1.y);
                a1.z = fmaf(w, v1.z, a1.z);
                a1.w = fmaf(w, v1.w, a1.w);
            }
        }
    }
}

__global__ void __launch_bounds__(256) dense_grid_kernel(
    const float* __restrict__ pts,
    const float* __restrict__ cb0,
    const float* __restrict__ cb1,
    const float* __restrict__ cb2,
    const float* __restrict__ cb3,
    const float* __restrict__ cb4,
    float* __restrict__ out,
    int n)
{
    int i = blockIdx.x * blockDim.x + threadIdx.x;
    if (i >= n) return;

    float px = pts[3 * i + 0];
    float py = pts[3 * i + 1];
    float pz = pts[3 * i + 2];

    float4 a0 = make_float4(0.f, 0.f, 0.f, 0.f);
    float4 a1 = make_float4(0.f, 0.f, 0.f, 0.f);

    lerp_add< 16>(cb0, px, py, pz, a0, a1);
    lerp_add< 32>(cb1, px, py, pz, a0, a1);
    lerp_add< 64>(cb2, px, py, pz, a0, a1);
    lerp_add<128>(cb3, px, py, pz, a0, a1);
    lerp_add<256>(cb4, px, py, pz, a0, a1);

    float4* o = reinterpret_cast<float4*>(out + (size_t)i * FEAT);
    o[0] = a0;
    o[1] = a1;
}

extern "C" void kernel_launch(void* const* d_in, const int* in_sizes, int n_in,
                              void* d_out, int out_size)
{
    const float* pts = (const float*)d_in[0];
    const float* cb0 = (const float*)d_in[1];
    const float* cb1 = (const float*)d_in[2];
    const float* cb2 = (const float*)d_in[3];
    const float* cb3 = (const float*)d_in[4];
    const float* cb4 = (const float*)d_in[5];
    float* out = (float*)d_out;

    int n = in_sizes[0] / 3;  // pts is [N,3]
    int threads = 256;
    int blocks = (n + threads - 1) / threads;
    dense_grid_kernel<<<blocks, threads>>>(pts, cb0, cb1, cb2, cb3, cb4, out, n);
}

// round 2
// speedup vs baseline: 1.5619x; 1.5619x over previous
#include <cuda_runtime.h>

// 16 lanes cooperate per point. Lane layout within group g = lane & 15:
//   dz = g>>3, dy = (g>>2)&1, sub = g&3
//   sub selects 16B within the 64B chunk [corner(dx=0) 32B | corner(dx=1) 32B]:
//     dx = sub>>1, feat-half = sub&1  (floats [idx*8 + sub*4, +4))
template<int RES>
__device__ __forceinline__ void lerp_add_coop(const float* __restrict__ cb,
                                              float px, float py, float pz,
                                              int dx, int dy, int dz, int sub,
                                              float4& acc)
{
    const float s = (float)(RES - 1);
    float x = px * s, y = py * s, z = pz * s;

    float fx0 = fminf(fmaxf(floorf(x), 0.0f), (float)(RES - 2));
    float fy0 = fminf(fmaxf(floorf(y), 0.0f), (float)(RES - 2));
    float fz0 = fminf(fmaxf(floorf(z), 0.0f), (float)(RES - 2));

    int x0 = (int)fx0, y0 = (int)fy0, z0 = (int)fz0;
    float fx = x - fx0, fy = y - fy0, fz = z - fz0;

    float w = (dx ? fx : 1.0f - fx) * (dy ? fy : 1.0f - fy) * (dz ? fz : 1.0f - fz);

    int idx = x0 + (y0 + dy) * RES + (z0 + dz) * (RES * RES);
    const float4* p = reinterpret_cast<const float4*>(cb) + ((size_t)idx * 2 + sub);
    float4 v = __ldg(p);

    acc.x = fmaf(w, v.x, acc.x);
    acc.y = fmaf(w, v.y, acc.y);
    acc.z = fmaf(w, v.z, acc.z);
    acc.w = fmaf(w, v.w, acc.w);
}

__global__ void __launch_bounds__(256) dense_grid_coop_kernel(
    const float* __restrict__ pts,
    const float* __restrict__ cb0,
    const float* __restrict__ cb1,
    const float* __restrict__ cb2,
    const float* __restrict__ cb3,
    const float* __restrict__ cb4,
    float* __restrict__ out,
    int n)
{
    int tid  = blockIdx.x * blockDim.x + threadIdx.x;
    int lane = threadIdx.x & 31;
    int g    = lane & 15;                 // lane within 16-lane point group
    int pt   = (tid >> 5) * 2 + (lane >> 4);

    bool valid = (pt < n);
    int ptc = valid ? pt : (n - 1);       // clamp so full warp executes shfl

    float px = pts[3 * ptc + 0];
    float py = pts[3 * ptc + 1];
    float pz = pts[3 * ptc + 2];

    int sub = g & 3;
    int dx  = sub >> 1;
    int dy  = (g >> 2) & 1;
    int dz  = g >> 3;

    float4 acc = make_float4(0.f, 0.f, 0.f, 0.f);

    lerp_add_coop< 16>(cb0, px, py, pz, dx, dy, dz, sub, acc);
    lerp_add_coop< 32>(cb1, px, py, pz, dx, dy, dz, sub, acc);
    lerp_add_coop< 64>(cb2, px, py, pz, dx, dy, dz, sub, acc);
    lerp_add_coop<128>(cb3, px, py, pz, dx, dy, dz, sub, acc);
    lerp_add_coop<256>(cb4, px, py, pz, dx, dy, dz, sub, acc);

    // Reduce the 8 partials per feature-half: xor over g bits 1,2,3
    // (keeps bit0 = feature-half invariant, stays within the 16-lane group).
    #pragma unroll
    for (int off = 2; off <= 8; off <<= 1) {
        acc.x += __shfl_xor_sync(0xffffffffu, acc.x, off);
        acc.y += __shfl_xor_sync(0xffffffffu, acc.y, off);
        acc.z += __shfl_xor_sync(0xffffffffu, acc.z, off);
        acc.w += __shfl_xor_sync(0xffffffffu, acc.w, off);
    }

    if (valid && g < 2) {
        // g==0 -> feats 0..3, g==1 -> feats 4..7
        float4* o = reinterpret_cast<float4*>(out + (size_t)pt * 8) + g;
        *o = acc;
    }
}

extern "C" void kernel_launch(void* const* d_in, const int* in_sizes, int n_in,
                              void* d_out, int out_size)
{
    const float* pts = (const float*)d_in[0];
    const float* cb0 = (const float*)d_in[1];
    const float* cb1 = (const float*)d_in[2];
    const float* cb2 = (const float*)d_in[3];
    const float* cb3 = (const float*)d_in[4];
    const float* cb4 = (const float*)d_in[5];
    float* out = (float*)d_out;

    int n = in_sizes[0] / 3;              // pts is [N,3]
    int total_threads = ((n + 1) / 2) * 32;  // 16 lanes per point, 2 points per warp
    int threads = 256;
    int blocks = (total_threads + threads - 1) / threads;
    dense_grid_coop_kernel<<<blocks, threads>>>(pts, cb0, cb1, cb2, cb3, cb4, out, n);
}

// round 3
// speedup vs baseline: 1.7588x; 1.1260x over previous
#include <cuda_runtime.h>

// 16 lanes cooperate per point. Lane layout within group g = lane & 15:
//   dz = g>>3, dy = (g>>2)&1, sub = g&3
//   sub selects 16B within the 64B chunk [corner(dx=0) 32B | corner(dx=1) 32B]
template<int RES, bool STREAM>
__device__ __forceinline__ void lerp_add_coop(const float* __restrict__ cb,
                                              float px, float py, float pz,
                                              int dx, int dy, int dz, int sub,
                                              float4& acc)
{
    const float s = (float)(RES - 1);
    float x = px * s, y = py * s, z = pz * s;

    float fx0 = fminf(fmaxf(floorf(x), 0.0f), (float)(RES - 2));
    float fy0 = fminf(fmaxf(floorf(y), 0.0f), (float)(RES - 2));
    float fz0 = fminf(fmaxf(floorf(z), 0.0f), (float)(RES - 2));

    int x0 = (int)fx0, y0 = (int)fy0, z0 = (int)fz0;
    float fx = x - fx0, fy = y - fy0, fz = z - fz0;

    float w = (dx ? fx : 1.0f - fx) * (dy ? fy : 1.0f - fy) * (dz ? fz : 1.0f - fz);

    int idx = x0 + (y0 + dy) * RES + (z0 + dz) * (RES * RES);
    const float4* p = reinterpret_cast<const float4*>(cb) + ((size_t)idx * 2 + sub);

    float4 v;
    if (STREAM) {
        // evict-first: don't let the 512MB cb4 stream thrash cb3's L2 residency
        v = __ldcs(p);
    } else {
        v = __ldg(p);
    }

    acc.x = fmaf(w, v.x, acc.x);
    acc.y = fmaf(w, v.y, acc.y);
    acc.z = fmaf(w, v.z, acc.z);
    acc.w = fmaf(w, v.w, acc.w);
}

__global__ void __launch_bounds__(256) dense_grid_coop_kernel(
    const float* __restrict__ pts,
    const float* __restrict__ cb0,
    const float* __restrict__ cb1,
    const float* __restrict__ cb2,
    const float* __restrict__ cb3,
    const float* __restrict__ cb4,
    float* __restrict__ out,
    int n)
{
    int tid  = blockIdx.x * blockDim.x + threadIdx.x;
    int lane = threadIdx.x & 31;
    int g    = lane & 15;                 // lane within 16-lane point group
    int pt   = (tid >> 5) * 2 + (lane >> 4);

    bool valid = (pt < n);
    int ptc = valid ? pt : (n - 1);       // clamp so full warp executes shfl

    float px = pts[3 * ptc + 0];
    float py = pts[3 * ptc + 1];
    float pz = pts[3 * ptc + 2];

    int sub = g & 3;
    int dx  = sub >> 1;
    int dy  = (g >> 2) & 1;
    int dz  = g >> 3;

    float4 acc = make_float4(0.f, 0.f, 0.f, 0.f);

    lerp_add_coop< 16, false>(cb0, px, py, pz, dx, dy, dz, sub, acc);
    lerp_add_coop< 32, false>(cb1, px, py, pz, dx, dy, dz, sub, acc);
    lerp_add_coop< 64, false>(cb2, px, py, pz, dx, dy, dz, sub, acc);
    lerp_add_coop<128, false>(cb3, px, py, pz, dx, dy, dz, sub, acc);
    lerp_add_coop<256, true >(cb4, px, py, pz, dx, dy, dz, sub, acc);

    // Reduce the 8 partials per feature-half: xor over g bits 1,2,3
    #pragma unroll
    for (int off = 2; off <= 8; off <<= 1) {
        acc.x += __shfl_xor_sync(0xffffffffu, acc.x, off);
        acc.y += __shfl_xor_sync(0xffffffffu, acc.y, off);
        acc.z += __shfl_xor_sync(0xffffffffu, acc.z, off);
        acc.w += __shfl_xor_sync(0xffffffffu, acc.w, off);
    }

    if (valid && g < 2) {
        float4* o = reinterpret_cast<float4*>(out + (size_t)pt * 8) + g;
        *o = acc;
    }
}

extern "C" void kernel_launch(void* const* d_in, const int* in_sizes, int n_in,
                              void* d_out, int out_size)
{
    const float* pts = (const float*)d_in[0];
    const float* cb0 = (const float*)d_in[1];
    const float* cb1 = (const float*)d_in[2];
    const float* cb2 = (const float*)d_in[3];
    const float* cb3 = (const float*)d_in[4];
    const float* cb4 = (const float*)d_in[5];
    float* out = (float*)d_out;

    int n = in_sizes[0] / 3;              // pts is [N,3]
    int total_threads = ((n + 1) / 2) * 32;  // 16 lanes per point, 2 points per warp
    int threads = 256;
    int blocks = (total_threads + threads - 1) / threads;
    dense_grid_coop_kernel<<<blocks, threads>>>(pts, cb0, cb1, cb2, cb3, cb4, out, n);
}